// round 2
// baseline (speedup 1.0000x reference)
#include <cuda_runtime.h>
#include <cuda_bf16.h>
#include <math.h>

// Problem constants
#define B 512
#define S 64
#define KNB 8
#define D 16
#define NSTEPS 100
#define NUNITS 128

// Scratch (device globals - no allocation allowed)
__device__ float g_urel[B * 64];            // user-relation mean-dot scores
__device__ float g_item[B * S * D];         // item embeddings per (b,s)

// ---------------------------------------------------------------------------
// Kernel A: urel[b][r] = (1/16) * sum_d usr_emb[u[b]][d] * rel_emb[r][d]
// grid=B, block=64
// ---------------------------------------------------------------------------
__global__ __launch_bounds__(64) void urel_kernel(
    const float* __restrict__ usr_emb, const float* __restrict__ rel_emb,
    const int* __restrict__ u)
{
    __shared__ float us[D];
    int b = blockIdx.x;
    int tid = threadIdx.x;
    if (tid < D) us[tid] = usr_emb[(size_t)u[b] * D + tid];
    __syncthreads();
    float s = 0.f;
#pragma unroll
    for (int d = 0; d < D; d++) s += us[d] * __ldg(rel_emb + tid * D + d);
    g_urel[b * 64 + tid] = s * (1.0f / 16.0f);
}

// ---------------------------------------------------------------------------
// Kernel B: full 2-hop KGCN aggregation for one (b,s) pair per block.
// grid = B*S (32768), block = 128
// ---------------------------------------------------------------------------
__global__ __launch_bounds__(128) void kgcn_kernel(
    const float* __restrict__ ent_emb,
    const float* __restrict__ agg_W, const float* __restrict__ agg_b,
    const int* __restrict__ click_seq,
    const int* __restrict__ adj_ent, const int* __restrict__ adj_rel)
{
    int bs = blockIdx.x;
    int b  = bs >> 6;            // /S
    int tid = threadIdx.x;

    __shared__ float urel[64];
    __shared__ int   e0s_sh;
    __shared__ int   e1s[8], r0s[8];
    __shared__ int   e2s[64], r1s[64];
    __shared__ float ev0[16];
    __shared__ float ev1[8][16];
    __shared__ float ev2[64][17];      // padded
    __shared__ float Wm[256];
    __shared__ float bb[16];
    __shared__ float sc1[64];
    __shared__ float p1[8][8];
    __shared__ float p0[8];
    __shared__ float tmp1[8][16];
    __shared__ float out1s[8][17];     // padded
    __shared__ float tmp0[16], out0[16], tmpf[16];

    // --- load broadcast params + first index ---
    if (tid < 64) urel[tid] = g_urel[b * 64 + tid];
    Wm[tid]        = agg_W[tid];
    Wm[tid + 128]  = agg_W[tid + 128];
    if (tid < 16) bb[tid] = agg_b[tid];
    if (tid == 0) e0s_sh = click_seq[bs];
    __syncthreads();

    int e0 = e0s_sh;
    if (tid < 8) {
        e1s[tid] = adj_ent[e0 * KNB + tid];
        r0s[tid] = adj_rel[e0 * KNB + tid];
    }
    if (tid < 16) ev0[tid] = __ldg(ent_emb + (size_t)e0 * D + tid);
    __syncthreads();

    // --- hop-2 indices + hop-1 embedding gather ---
    if (tid < 64) {
        int n = tid >> 3, k = tid & 7;
        int e1n = e1s[n];
        e2s[tid] = adj_ent[e1n * KNB + k];
        r1s[tid] = adj_rel[e1n * KNB + k];
    }
    if (tid < 32) {
        int row = tid >> 2, c = tid & 3;
        float4 v = __ldg(((const float4*)ent_emb) + (size_t)e1s[row] * 4 + c);
        ev1[row][c * 4 + 0] = v.x;
        ev1[row][c * 4 + 1] = v.y;
        ev1[row][c * 4 + 2] = v.z;
        ev1[row][c * 4 + 3] = v.w;
    }
    __syncthreads();

    // --- hop-2 embedding gather (the hot 128MB random-read) ---
#pragma unroll
    for (int f = tid; f < 256; f += 128) {
        int row = f >> 2, c = f & 3;
        float4 v = __ldg(((const float4*)ent_emb) + (size_t)e2s[row] * 4 + c);
        ev2[row][c * 4 + 0] = v.x;
        ev2[row][c * 4 + 1] = v.y;
        ev2[row][c * 4 + 2] = v.z;
        ev2[row][c * 4 + 3] = v.w;
    }
    if (tid < 64) sc1[tid] = 0.f; // placeholder; filled next phase after sync
    __syncthreads();

    // --- scores (just urel lookups) + softmaxes ---
    if (tid < 64) sc1[tid] = urel[r1s[tid]];
    __syncthreads();

    if (tid < 8) {
        // softmax over sc1[tid*8 .. tid*8+7]
        float m = -1e30f;
#pragma unroll
        for (int k = 0; k < 8; k++) m = fmaxf(m, sc1[tid * 8 + k]);
        float e[8], sum = 0.f;
#pragma unroll
        for (int k = 0; k < 8; k++) { e[k] = expf(sc1[tid * 8 + k] - m); sum += e[k]; }
        float inv = 1.f / sum;
#pragma unroll
        for (int k = 0; k < 8; k++) p1[tid][k] = e[k] * inv;
    } else if (tid == 8) {
        float sc[8], m = -1e30f;
#pragma unroll
        for (int k = 0; k < 8; k++) { sc[k] = urel[r0s[k]]; m = fmaxf(m, sc[k]); }
        float e[8], sum = 0.f;
#pragma unroll
        for (int k = 0; k < 8; k++) { e[k] = expf(sc[k] - m); sum += e[k]; }
        float inv = 1.f / sum;
#pragma unroll
        for (int k = 0; k < 8; k++) p0[k] = e[k] * inv;
    }
    __syncthreads();

    // --- hop1 (i=0): weighted neighbor sum + self ---
    {
        int n = tid >> 4, d = tid & 15;
        float a = 0.f;
#pragma unroll
        for (int k = 0; k < 8; k++) a += p1[n][k] * ev2[n * 8 + k][d];
        tmp1[n][d] = ev1[n][d] + a;
    }
    __syncthreads();

    // --- hop1 linear + sigmoid ---
    {
        int n = tid >> 4, dp = tid & 15;
        float a = bb[dp];
#pragma unroll
        for (int d = 0; d < 16; d++) a += tmp1[n][d] * Wm[d * 16 + dp];
        out1s[n][dp] = 1.f / (1.f + expf(-a));
    }
    __syncthreads();

    // --- hop0 (i=0): aggregate ev1 with p0, sigmoid ---
    if (tid < 16) {
        float a = 0.f;
#pragma unroll
        for (int k = 0; k < 8; k++) a += p0[k] * ev1[k][tid];
        tmp0[tid] = ev0[tid] + a;
    }
    __syncthreads();
    if (tid < 16) {
        float a = bb[tid];
#pragma unroll
        for (int d = 0; d < 16; d++) a += tmp0[d] * Wm[d * 16 + tid];
        out0[tid] = 1.f / (1.f + expf(-a));
    }
    __syncthreads();

    // --- i=1 hop0: aggregate out1 with the SAME p0, tanh, relu, store ---
    if (tid < 16) {
        float a = 0.f;
#pragma unroll
        for (int k = 0; k < 8; k++) a += p0[k] * out1s[k][tid];
        tmpf[tid] = out0[tid] + a;
    }
    __syncthreads();
    if (tid < 16) {
        float a = bb[tid];
#pragma unroll
        for (int d = 0; d < 16; d++) a += tmpf[d] * Wm[d * 16 + tid];
        float it = tanhf(a);
        it = fmaxf(it, 0.f);
        g_item[(size_t)bs * D + tid] = it;
    }
}

// ---------------------------------------------------------------------------
// Kernel C: per-batch finalize: S-reduction + fc head + diffusion MLP branch.
// grid=B, block=128
// ---------------------------------------------------------------------------
__global__ __launch_bounds__(128) void final_kernel(
    const float* __restrict__ usr_emb, const float* __restrict__ ent_emb,
    const float* __restrict__ fc1_W, const float* __restrict__ fc1_b,
    const float* __restrict__ fc2_W, const float* __restrict__ fc2_b,
    const float* __restrict__ W1, const float* __restrict__ b1,
    const float* __restrict__ W2, const float* __restrict__ b2,
    const float* __restrict__ W3, const float* __restrict__ b3,
    const float* __restrict__ W4, const float* __restrict__ b4,
    const float* __restrict__ se1, const float* __restrict__ se2,
    const float* __restrict__ se3,
    const float* __restrict__ noise_e,
    const int* __restrict__ u, const int* __restrict__ v,
    const int* __restrict__ t,
    float* __restrict__ out)
{
    int b = blockIdx.x;
    int tid = threadIdx.x;
    __shared__ float xs[16], h1[128], h2[128], h3[128];
    __shared__ float psum[8][16], pmax[8][16];
    __shared__ float fus[32], hh[64], prod[16];
    __shared__ float ab_sh, omb_sh;

    int tb = t[b];
    if (tid == 0) {
        float ap = 1.f;
        for (int i = 0; i <= tb; i++) {
            float z = -6.f + 12.f * (float)i / 99.f;
            float beta = (1.f / (1.f + expf(-z))) * (0.005f - 1e-5f) + 1e-5f;
            ap *= (1.f - beta);
        }
        ab_sh = sqrtf(ap);
        omb_sh = sqrtf(1.f - ap);
    }
    __syncthreads();
    float ab = ab_sh, omb = omb_sh;

    if (tid < 16)
        xs[tid] = usr_emb[(size_t)u[b] * D + tid] * ab + noise_e[b * D + tid] * omb;
    __syncthreads();

    // diffusion MLP layer 1 (16 -> 128)
    {
        float a = b1[tid] + se1[tb * NUNITS + tid];
#pragma unroll
        for (int d = 0; d < 16; d++) a += xs[d] * W1[d * NUNITS + tid];
        h1[tid] = fmaxf(a, 0.f);
    }
    __syncthreads();
    // layer 2 (128 -> 128)
    {
        float a = b2[tid] + se2[tb * NUNITS + tid];
        for (int i = 0; i < 128; i++) a += h1[i] * W2[i * NUNITS + tid];
        h2[tid] = fmaxf(a, 0.f);
    }
    __syncthreads();
    // layer 3 (128 -> 128)
    {
        float a = b3[tid] + se3[tb * NUNITS + tid];
        for (int i = 0; i < 128; i++) a += h2[i] * W3[i * NUNITS + tid];
        h3[tid] = fmaxf(a, 0.f);
    }
    __syncthreads();
    // layer 4 (128 -> 16), write diff_out into out[:, 1:17]
    if (tid < 16) {
        float a = b4[tid];
        for (int i = 0; i < 128; i++) a += h3[i] * W4[i * D + tid];
        out[b * (1 + D) + 1 + tid] = a;
    }

    // --- item_emb reduction over S (deterministic) ---
    {
        int d = tid & 15, sc = tid >> 4;
        float s = 0.f, m = -1e30f;
#pragma unroll
        for (int j = 0; j < 8; j++) {
            float vv = g_item[((size_t)b * S + sc * 8 + j) * D + d];
            s += vv;
            m = fmaxf(m, vv);
        }
        psum[sc][d] = s;
        pmax[sc][d] = m;
    }
    __syncthreads();
    if (tid < 16) {
        float s = 0.f, m = -1e30f;
#pragma unroll
        for (int c = 0; c < 8; c++) { s += psum[c][tid]; m = fmaxf(m, pmax[c][tid]); }
        fus[tid]      = fmaxf(s, 0.f);
        fus[16 + tid] = fmaxf(m, 0.f);
    }
    __syncthreads();

    // fc1: [32] -> [64]
    if (tid < 64) {
        float a = fc1_b[tid];
#pragma unroll
        for (int i = 0; i < 32; i++) a += fus[i] * fc1_W[i * 64 + tid];
        hh[tid] = fmaxf(a, 0.f);
    }
    __syncthreads();
    // fc2: [64] -> [16], then elementwise * ent_emb[v[b]]
    if (tid < 16) {
        float a = fc2_b[tid];
#pragma unroll
        for (int i = 0; i < 64; i++) a += hh[i] * fc2_W[i * D + tid];
        float f = fmaxf(a, 0.f);
        prod[tid] = f * __ldg(ent_emb + (size_t)v[b] * D + tid);
    }
    __syncthreads();
    if (tid == 0) {
        float s = 0.f;
#pragma unroll
        for (int i = 0; i < 16; i++) s += prod[i];
        out[b * (1 + D)] = 1.f / (1.f + expf(-s));
    }
}

// ---------------------------------------------------------------------------
extern "C" void kernel_launch(void* const* d_in, const int* in_sizes, int n_in,
                              void* d_out, int out_size)
{
    const float* usr_emb  = (const float*)d_in[0];
    const float* ent_emb  = (const float*)d_in[1];
    const float* rel_emb  = (const float*)d_in[2];
    const float* agg_W    = (const float*)d_in[3];
    const float* agg_b    = (const float*)d_in[4];
    const float* fc1_W    = (const float*)d_in[5];
    const float* fc1_b    = (const float*)d_in[6];
    const float* fc2_W    = (const float*)d_in[7];
    const float* fc2_b    = (const float*)d_in[8];
    const float* mlp_W1   = (const float*)d_in[9];
    const float* mlp_b1   = (const float*)d_in[10];
    const float* mlp_W2   = (const float*)d_in[11];
    const float* mlp_b2   = (const float*)d_in[12];
    const float* mlp_W3   = (const float*)d_in[13];
    const float* mlp_b3   = (const float*)d_in[14];
    const float* mlp_W4   = (const float*)d_in[15];
    const float* mlp_b4   = (const float*)d_in[16];
    const float* se1      = (const float*)d_in[17];
    const float* se2      = (const float*)d_in[18];
    const float* se3      = (const float*)d_in[19];
    const float* noise_e  = (const float*)d_in[20];
    const int*   u        = (const int*)d_in[21];
    const int*   v        = (const int*)d_in[22];
    const int*   click    = (const int*)d_in[23];
    const int*   adj_ent  = (const int*)d_in[24];
    const int*   adj_rel  = (const int*)d_in[25];
    const int*   t        = (const int*)d_in[26];
    float* out = (float*)d_out;

    urel_kernel<<<B, 64>>>(usr_emb, rel_emb, u);
    kgcn_kernel<<<B * S, 128>>>(ent_emb, agg_W, agg_b, click, adj_ent, adj_rel);
    final_kernel<<<B, 128>>>(usr_emb, ent_emb, fc1_W, fc1_b, fc2_W, fc2_b,
                             mlp_W1, mlp_b1, mlp_W2, mlp_b2, mlp_W3, mlp_b3,
                             mlp_W4, mlp_b4, se1, se2, se3, noise_e,
                             u, v, t, out);
}